// round 15
// baseline (speedup 1.0000x reference)
#include <cuda_runtime.h>
#include <math.h>
#include <stdint.h>

#define T_TOKENS 2048
#define HID 2048
#define NEXP 32
#define TOPK 8
#define INTER_SZ 768
#define NGU 1536
#define THRESH 0.8f
#define LAMBDA 1.000345f   // compensation for tf32 RZ-truncation of B operands

#define BM 64
#define TK 32
#define ROWF 36   // padded floats per smem row (32 + 4); 144B row stride

// ---------------- scratch (static device globals; no allocation) -------------
__device__ int   g_count[NEXP];
__device__ int   g_tokens[NEXP][T_TOKENS];
__device__ int   g_tok_nkeep[T_TOKENS];
__device__ int   g_tok_expert[T_TOKENS][TOPK];
__device__ int   g_tok_slot[T_TOKENS][TOPK];
__device__ float g_tok_w[T_TOKENS][TOPK];
__device__ __align__(128) float g_xcvt[T_TOKENS][HID];                 // RNA(lambda * x)
__device__ __align__(128) float g_h[NEXP][T_TOKENS][INTER_SZ];        // RNA(lambda * silu(g)*u)
__device__ __align__(128) float g_downbuf[(size_t)NEXP * T_TOKENS * HID];

// ---------------- helpers ----------------------------------------------------
__device__ __forceinline__ uint32_t cvt_tf32(float f) {
    uint32_t r;
    asm("cvt.rna.tf32.f32 %0, %1;" : "=r"(r) : "f"(f));
    return r;
}
__device__ __forceinline__ void cpasync16(uint32_t dst, const void* src) {
    asm volatile("cp.async.cg.shared.global [%0], [%1], 16;" :: "r"(dst), "l"(src));
}
__device__ __forceinline__ uint32_t smem_u32(const void* p) {
    uint32_t a;
    asm("{ .reg .u64 t; cvta.to.shared.u64 t, %1; cvt.u32.u64 %0, t; }" : "=r"(a) : "l"(p));
    return a;
}
__device__ __forceinline__ void ldsm4(uint32_t& r0, uint32_t& r1, uint32_t& r2, uint32_t& r3,
                                      uint32_t addr) {
    asm volatile("ldmatrix.sync.aligned.m8n8.x4.shared.b16 {%0,%1,%2,%3}, [%4];"
                 : "=r"(r0), "=r"(r1), "=r"(r2), "=r"(r3) : "r"(addr));
}
__device__ __forceinline__ void mma8(float* d, const uint32_t* a, const uint32_t* b) {
    asm volatile(
        "mma.sync.aligned.m16n8k8.row.col.f32.tf32.tf32.f32 "
        "{%0,%1,%2,%3}, {%4,%5,%6,%7}, {%8,%9}, {%0,%1,%2,%3};"
        : "+f"(d[0]), "+f"(d[1]), "+f"(d[2]), "+f"(d[3])
        : "r"(a[0]), "r"(a[1]), "r"(a[2]), "r"(a[3]), "r"(b[0]), "r"(b[1]));
}
__device__ __forceinline__ float silu(float g) {
    return g * (1.f / (1.f + __expf(-g)));
}

// ---------------- kernel 0: zero counts -------------------------------------
__global__ void zero_counts_kernel() {
    if (threadIdx.x < NEXP) g_count[threadIdx.x] = 0;
}

// ---------------- kernel 1: router + hidden pre-convert ----------------------
__global__ void router_kernel(const float* __restrict__ x,
                              const float* __restrict__ gw) {
    __shared__ float xs[HID];
    __shared__ float logits[NEXP];
    int t = blockIdx.x;
    const float* xp = x + (size_t)t * HID;
    for (int i = threadIdx.x; i < HID; i += blockDim.x) xs[i] = xp[i];
    __syncthreads();

    // pre-convert this token's row to RNA(lambda*x) while logits compute
    for (int i = threadIdx.x; i < HID; i += blockDim.x)
        ((uint32_t*)g_xcvt[t])[i] = cvt_tf32(LAMBDA * xs[i]);

    int warp = threadIdx.x >> 5, lane = threadIdx.x & 31;
    #pragma unroll
    for (int eo = 0; eo < 4; eo++) {
        int e = warp * 4 + eo;
        const float* w = gw + (size_t)e * HID;
        float s = 0.f;
        for (int j = lane; j < HID; j += 32) s += xs[j] * w[j];
        #pragma unroll
        for (int o = 16; o; o >>= 1) s += __shfl_xor_sync(0xffffffffu, s, o);
        if (lane == 0) logits[e] = s;
    }
    __syncthreads();

    if (threadIdx.x == 0) {
        float p[NEXP];
        float mx = -1e30f;
        #pragma unroll
        for (int e = 0; e < NEXP; e++) mx = fmaxf(mx, logits[e]);
        float sum = 0.f;
        #pragma unroll
        for (int e = 0; e < NEXP; e++) { p[e] = expf(logits[e] - mx); sum += p[e]; }
        float inv = 1.f / sum;
        #pragma unroll
        for (int e = 0; e < NEXP; e++) p[e] *= inv;

        float tv[TOPK]; int ti[TOPK];
        #pragma unroll
        for (int k = 0; k < TOPK; k++) {
            float best = -1.f; int bi = 0;
            #pragma unroll
            for (int e = 0; e < NEXP; e++)
                if (p[e] > best) { best = p[e]; bi = e; }
            tv[k] = best; ti[k] = bi; p[bi] = -1.f;
        }
        float s8 = 0.f;
        #pragma unroll
        for (int k = 0; k < TOPK; k++) s8 += tv[k];
        float invs8 = 1.f / fmaxf(s8, 1e-12f);
        float cum = 0.f; int cnt_lt = 0;
        #pragma unroll
        for (int k = 0; k < TOPK; k++) {
            cum += tv[k] * invs8;
            if (cum < THRESH) cnt_lt++;
        }
        int keep = min(cnt_lt + 1, TOPK);
        float ssel = 0.f;
        for (int k = 0; k < keep; k++) ssel += tv[k];
        float invsel = 1.f / fmaxf(ssel, 1e-12f);
        g_tok_nkeep[t] = keep;
        for (int k = 0; k < keep; k++) {
            int e = ti[k];
            int slot = atomicAdd(&g_count[e], 1);
            g_tokens[e][slot]   = t;
            g_tok_expert[t][k]  = e;
            g_tok_slot[t][k]    = slot;
            g_tok_w[t][k]       = tv[k] * invsel;
        }
    }
}

// ---------------- mma.sync tf32 grouped GEMM, 128thr x 3 CTAs/SM -------------
// 4 warps in 2(m) x 2(n); warp tile 32 x (32|64); BM=64. 2-deep rings, two
// barriers per stage. NEW vs R14: __launch_bounds__(128,3) raises the reg cap
// to 170, and fragments are DOUBLE-BUFFERED across kk so each kk's ldsm drains
// under the previous kk's mma stream (ILP latency hiding instead of raw
// scoreboard stalls at regs=128).
// B operands are RAW fp32 bits (tf32 mma truncates; compensated by LAMBDA).
// FUSED=true: BN=64/matrix (gate+up) -> tf32 g_h. FUSED=false: BN=128 -> f32.
template<bool FUSED>
__global__ __launch_bounds__(128, 3)
void moe_mma(const float* __restrict__ W) {
    constexpr int KDIM = FUSED ? HID : INTER_SZ;
    constexpr int NS   = KDIM / TK;              // 64 or 24
    constexpr int BNK  = FUSED ? 64 : 128;       // B0 rows per tile
    constexpr int NJ   = FUSED ? 4 : 8;          // 8-col mma tiles per warp
    constexpr int NJ1  = FUSED ? 4 : 1;
    constexpr int WN   = FUSED ? 32 : 64;        // warp N extent
    constexpr int NA   = 4;                      // A chunks/thread (64*8/128)
    constexpr int NB0  = BNK * 8 / 128;          // 4 or 8
    constexpr int BROWS = 128;                   // total B rows staged (B0[+B1])

    const int e   = blockIdx.z;
    const int cnt = g_count[e];
    const int m0  = blockIdx.y * BM;
    if (m0 >= cnt) return;
    const int n0  = blockIdx.x * BNK;

    extern __shared__ float smf[];
    int*  toks = (int*)(smf + 2 * (BM + BROWS) * ROWF);

    const int tid  = threadIdx.x;
    const int lane = tid & 31, wid = tid >> 5;
    const int warp_m = wid & 1, warp_n = wid >> 1;           // 2 x 2 warps

    if (FUSED && tid < BM) {
        int r = m0 + tid;
        toks[tid] = (r < cnt) ? g_tokens[e][r] : g_tokens[e][0];
    }
    __syncthreads();

    const uint32_t sa  = smem_u32(smf);
    const uint32_t aAs = sa;                                 // A: [2][64][ROWF]
    const uint32_t aB0 = sa + 2 * BM * ROWF * 4;             // B0: [2][BNK][ROWF]
    const uint32_t aB1 = aB0 + 2 * BNK * ROWF * 4;           // B1 (FUSED): [2][64][ROWF]

    const float* Wb = W + (size_t)e * (FUSED ? (size_t)NGU * HID : (size_t)HID * INTER_SZ)
                        + (size_t)n0 * KDIM;
    const float* Wu = FUSED ? (W + (size_t)e * NGU * HID + (size_t)(INTER_SZ + n0) * HID)
                            : (const float*)nullptr;

    // per-thread ldsm base offsets (bytes within a buffer)
    const int grp = lane >> 3, rr = lane & 7;
    const uint32_t abase = (uint32_t)(((warp_m * 32 + (grp & 1) * 8 + rr) * ROWF
                                       + (grp >> 1) * 4) * 4);
    const uint32_t bbase = (uint32_t)(((warp_n * WN + (grp >> 1) * 8 + rr) * ROWF
                                       + (grp & 1) * 4) * 4);

    // ---- A + B staging via cp.async; 2-deep rings, one commit group/stage ----
    auto stage = [&](int s) {
        const int buf = s & 1;
        const int k0  = s * TK;
        const uint32_t bufA = aAs + buf * BM * ROWF * 4;
        #pragma unroll
        for (int i = 0; i < NA; i++) {                       // A: 512 chunks / 128 thr
            int c = tid + i * 128; int row = c >> 3, q = c & 7;
            const float* src;
            if (FUSED) {
                src = &g_xcvt[toks[row]][k0 + q * 4];
            } else {
                int r = m0 + row; if (r >= cnt) r = m0;
                src = &g_h[e][r][k0 + q * 4];
            }
            cpasync16(bufA + (row * ROWF + q * 4) * 4, src);
        }
        const uint32_t bufB0 = aB0 + buf * BNK * ROWF * 4;
        #pragma unroll
        for (int i = 0; i < NB0; i++) {                      // B0: BNK*8 chunks
            int c = tid + i * 128; int row = c >> 3, q = c & 7;
            cpasync16(bufB0 + (row * ROWF + q * 4) * 4,
                      Wb + (size_t)row * KDIM + k0 + q * 4);
        }
        if (FUSED) {
            const uint32_t bufB1 = aB1 + buf * 64 * ROWF * 4;
            #pragma unroll
            for (int i = 0; i < 4; i++) {                    // B1: 512 chunks
                int c = tid + i * 128; int row = c >> 3, q = c & 7;
                cpasync16(bufB1 + (row * ROWF + q * 4) * 4,
                          Wu + (size_t)row * KDIM + k0 + q * 4);
            }
        }
        asm volatile("cp.async.commit_group;" ::: "memory");
    };

    float acc0[2][NJ][4] = {};
    float acc1[2][NJ1][4] = {};

    // double-buffered fragment registers (ping-pong across kk)
    uint32_t aF[2][2][4];
    uint32_t b0F[2][NJ][2];
    uint32_t b1F[2][NJ1][2];

    // ---- prologue ----
    stage(0);
    stage(1);

    for (int s = 0; s < NS; s++) {
        if (s + 1 < NS) asm volatile("cp.async.wait_group 1;" ::: "memory");
        else            asm volatile("cp.async.wait_group 0;" ::: "memory");
        __syncthreads();

        const uint32_t bufA  = aAs + (s & 1) * BM * ROWF * 4;
        const uint32_t bufB0 = aB0 + (s & 1) * BNK * ROWF * 4;
        const uint32_t bufB1 = aB1 + (s & 1) * 64 * ROWF * 4;

        // fragment loader for one kk slice into buffer pb
        auto ldfrag = [&](int kk, int pb) {
            #pragma unroll
            for (int i = 0; i < 2; i++)
                ldsm4(aF[pb][i][0], aF[pb][i][1], aF[pb][i][2], aF[pb][i][3],
                      bufA + abase + i * 16 * ROWF * 4 + kk * 32);
            #pragma unroll
            for (int jp = 0; jp < NJ / 2; jp++)
                ldsm4(b0F[pb][2 * jp][0], b0F[pb][2 * jp][1],
                      b0F[pb][2 * jp + 1][0], b0F[pb][2 * jp + 1][1],
                      bufB0 + bbase + jp * 16 * ROWF * 4 + kk * 32);
            if (FUSED) {
                #pragma unroll
                for (int jp = 0; jp < NJ1 / 2; jp++)
                    ldsm4(b1F[pb][2 * jp][0], b1F[pb][2 * jp][1],
                          b1F[pb][2 * jp + 1][0], b1F[pb][2 * jp + 1][1],
                          bufB1 + bbase + jp * 16 * ROWF * 4 + kk * 32);
            }
        };

        ldfrag(0, 0);
        #pragma unroll
        for (int kk = 0; kk < 4; kk++) {
            const int cur = kk & 1;
            if (kk < 3) ldfrag(kk + 1, cur ^ 1);   // prefetch next slice
            #pragma unroll
            for (int i = 0; i < 2; i++)
                #pragma unroll
                for (int j = 0; j < NJ; j++) {
                    mma8(acc0[i][j], aF[cur][i], b0F[cur][j]);
                    if (FUSED) mma8(acc1[i][j % NJ1], aF[cur][i], b1F[cur][j % NJ1]);
                }
        }

        // second barrier: all reads of buf s&1 done; stage(s+2) may overwrite it
        __syncthreads();
        if (s + 2 < NS) stage(s + 2);
    }

    // ---- epilogue ----
    #pragma unroll
    for (int i = 0; i < 2; i++) {
        int r0 = m0 + warp_m * 32 + i * 16 + (lane >> 2);
        #pragma unroll
        for (int j = 0; j < NJ; j++) {
            int col = n0 + warp_n * WN + j * 8 + 2 * (lane & 3);
            if (FUSED) {
                if (r0 < cnt) {
                    float2 v;
                    v.x = __uint_as_float(cvt_tf32(LAMBDA * silu(acc0[i][j][0]) * acc1[i][j % NJ1][0]));
                    v.y = __uint_as_float(cvt_tf32(LAMBDA * silu(acc0[i][j][1]) * acc1[i][j % NJ1][1]));
                    *(float2*)&g_h[e][r0][col] = v;
                }
                if (r0 + 8 < cnt) {
                    float2 v;
                    v.x = __uint_as_float(cvt_tf32(LAMBDA * silu(acc0[i][j][2]) * acc1[i][j % NJ1][2]));
                    v.y = __uint_as_float(cvt_tf32(LAMBDA * silu(acc0[i][j][3]) * acc1[i][j % NJ1][3]));
                    *(float2*)&g_h[e][r0 + 8][col] = v;
                }
            } else {
                if (r0 < cnt) {
                    float2 v = make_float2(acc0[i][j][0], acc0[i][j][1]);
                    *(float2*)&g_downbuf[((size_t)e * T_TOKENS + r0) * HID + col] = v;
                }
                if (r0 + 8 < cnt) {
                    float2 v = make_float2(acc0[i][j][2], acc0[i][j][3]);
                    *(float2*)&g_downbuf[((size_t)e * T_TOKENS + r0 + 8) * HID + col] = v;
                }
            }
        }
    }
}

// ---------------- kernel 4: deterministic per-token combine -----------------
__global__ void combine_kernel(float* __restrict__ out) {
    int t = blockIdx.x;
    int nk = g_tok_nkeep[t];
    int   es[TOPK], ss[TOPK];
    float ws[TOPK];
    for (int k = 0; k < nk; k++) {
        es[k] = g_tok_expert[t][k];
        ss[k] = g_tok_slot[t][k];
        ws[k] = g_tok_w[t][k];
    }
    for (int h = threadIdx.x * 4; h < HID; h += blockDim.x * 4) {
        float4 acc = make_float4(0.f, 0.f, 0.f, 0.f);
        for (int k = 0; k < nk; k++) {
            const float4 v = *(const float4*)
                &g_downbuf[((size_t)es[k] * T_TOKENS + ss[k]) * HID + h];
            acc.x += ws[k] * v.x; acc.y += ws[k] * v.y;
            acc.z += ws[k] * v.z; acc.w += ws[k] * v.w;
        }
        *(float4*)&out[(size_t)t * HID + h] = acc;
    }
}

// ---------------- launch ----------------------------------------------------
// 2 rings x (A 64 + B 128 rows) x ROWF floats = 13824 floats + 64 toks
#define SMEM_BYTES (2 * (64 + 128) * ROWF * 4 + 64 * 4)   // 55552 B; 3 CTAs/SM

extern "C" void kernel_launch(void* const* d_in, const int* in_sizes, int n_in,
                              void* d_out, int out_size) {
    const float* hidden  = (const float*)d_in[0];   // [2,1024,2048]
    const float* gate_w  = (const float*)d_in[1];   // [32,2048]
    const float* gate_up = (const float*)d_in[2];   // [32,1536,2048]
    const float* down_w  = (const float*)d_in[3];   // [32,2048,768]
    float* out = (float*)d_out;

    cudaFuncSetAttribute(moe_mma<true>,  cudaFuncAttributeMaxDynamicSharedMemorySize, SMEM_BYTES);
    cudaFuncSetAttribute(moe_mma<false>, cudaFuncAttributeMaxDynamicSharedMemorySize, SMEM_BYTES);

    zero_counts_kernel<<<1, 32>>>();
    router_kernel<<<T_TOKENS, 256>>>(hidden, gate_w);
    {
        dim3 grid(INTER_SZ / 64, T_TOKENS / BM, NEXP);    // (12, 32, 32)
        moe_mma<true><<<grid, 128, SMEM_BYTES>>>(gate_up);
    }
    {
        dim3 grid(HID / 128, T_TOKENS / BM, NEXP);        // (16, 32, 32)
        moe_mma<false><<<grid, 128, SMEM_BYTES>>>(down_w);
    }
    combine_kernel<<<T_TOKENS, 256>>>(out);
}

// round 17
// speedup vs baseline: 1.1303x; 1.1303x over previous
#include <cuda_runtime.h>
#include <math.h>
#include <stdint.h>

#define T_TOKENS 2048
#define HID 2048
#define NEXP 32
#define TOPK 8
#define INTER_SZ 768
#define NGU 1536
#define THRESH 0.8f
#define LAMBDA 1.000345f   // compensation for tf32 RZ-truncation of B operands

#define BM 64
#define TK 32
#define ROWF 36   // padded floats per smem row (32 + 4); 144B row stride

// ---------------- scratch (static device globals; no allocation) -------------
__device__ int   g_count[NEXP];
__device__ int   g_tokens[NEXP][T_TOKENS];
__device__ int   g_tok_nkeep[T_TOKENS];
__device__ int   g_tok_expert[T_TOKENS][TOPK];
__device__ int   g_tok_slot[T_TOKENS][TOPK];
__device__ float g_tok_w[T_TOKENS][TOPK];
__device__ __align__(128) float g_xcvt[T_TOKENS][HID];                 // RNA(lambda * x)
__device__ __align__(128) float g_h[NEXP][T_TOKENS][INTER_SZ];        // RNA(lambda * silu(g)*u)
__device__ __align__(128) float g_downbuf[(size_t)NEXP * T_TOKENS * HID];

// ---------------- helpers ----------------------------------------------------
__device__ __forceinline__ uint32_t cvt_tf32(float f) {
    uint32_t r;
    asm("cvt.rna.tf32.f32 %0, %1;" : "=r"(r) : "f"(f));
    return r;
}
__device__ __forceinline__ void cpasync16(uint32_t dst, const void* src) {
    asm volatile("cp.async.cg.shared.global [%0], [%1], 16;" :: "r"(dst), "l"(src));
}
__device__ __forceinline__ uint32_t smem_u32(const void* p) {
    uint32_t a;
    asm("{ .reg .u64 t; cvta.to.shared.u64 t, %1; cvt.u32.u64 %0, t; }" : "=r"(a) : "l"(p));
    return a;
}
__device__ __forceinline__ void ldsm4(uint32_t& r0, uint32_t& r1, uint32_t& r2, uint32_t& r3,
                                      uint32_t addr) {
    asm volatile("ldmatrix.sync.aligned.m8n8.x4.shared.b16 {%0,%1,%2,%3}, [%4];"
                 : "=r"(r0), "=r"(r1), "=r"(r2), "=r"(r3) : "r"(addr));
}
__device__ __forceinline__ void mma8(float* d, const uint32_t* a, const uint32_t* b) {
    asm volatile(
        "mma.sync.aligned.m16n8k8.row.col.f32.tf32.tf32.f32 "
        "{%0,%1,%2,%3}, {%4,%5,%6,%7}, {%8,%9}, {%0,%1,%2,%3};"
        : "+f"(d[0]), "+f"(d[1]), "+f"(d[2]), "+f"(d[3])
        : "r"(a[0]), "r"(a[1]), "r"(a[2]), "r"(a[3]), "r"(b[0]), "r"(b[1]));
}
__device__ __forceinline__ float silu(float g) {
    return g * (1.f / (1.f + __expf(-g)));
}

// ---- mbarrier primitives (base ISA; no 'a' features) ----
#define MBAR_INIT(addr, cnt) \
    asm volatile("mbarrier.init.shared.b64 [%0], %1;" :: "r"(addr), "r"(cnt) : "memory")
#define MBAR_ARRIVE(addr) \
    asm volatile("mbarrier.arrive.shared.b64 _, [%0];" :: "r"(addr) : "memory")
// .noinc: the async arrival CONSUMES the pre-initialized count (does NOT
// increment first). Without .noinc each thread is net-zero and the barrier
// never flips -> deadlock (R16).
#define CPASYNC_MBAR_ARRIVE(addr) \
    asm volatile("cp.async.mbarrier.arrive.noinc.shared.b64 [%0];" :: "r"(addr) : "memory")
__device__ __forceinline__ void mbar_wait(uint32_t addr, uint32_t parity) {
    asm volatile(
        "{\n\t.reg .pred P1;\n\t"
        "WL_%=:\n\t"
        "mbarrier.try_wait.parity.acquire.cta.shared::cta.b64 P1, [%0], %1, 0x989680;\n\t"
        "@P1 bra.uni WD_%=;\n\t"
        "bra.uni WL_%=;\n\t"
        "WD_%=:\n\t}"
        :: "r"(addr), "r"(parity) : "memory");
}

// ---------------- kernel 0: zero counts -------------------------------------
__global__ void zero_counts_kernel() {
    if (threadIdx.x < NEXP) g_count[threadIdx.x] = 0;
}

// ---------------- kernel 1: router + hidden pre-convert ----------------------
__global__ void router_kernel(const float* __restrict__ x,
                              const float* __restrict__ gw) {
    __shared__ float xs[HID];
    __shared__ float logits[NEXP];
    int t = blockIdx.x;
    const float* xp = x + (size_t)t * HID;
    for (int i = threadIdx.x; i < HID; i += blockDim.x) xs[i] = xp[i];
    __syncthreads();

    // pre-convert this token's row to RNA(lambda*x) while logits compute
    for (int i = threadIdx.x; i < HID; i += blockDim.x)
        ((uint32_t*)g_xcvt[t])[i] = cvt_tf32(LAMBDA * xs[i]);

    int warp = threadIdx.x >> 5, lane = threadIdx.x & 31;
    #pragma unroll
    for (int eo = 0; eo < 4; eo++) {
        int e = warp * 4 + eo;
        const float* w = gw + (size_t)e * HID;
        float s = 0.f;
        for (int j = lane; j < HID; j += 32) s += xs[j] * w[j];
        #pragma unroll
        for (int o = 16; o; o >>= 1) s += __shfl_xor_sync(0xffffffffu, s, o);
        if (lane == 0) logits[e] = s;
    }
    __syncthreads();

    if (threadIdx.x == 0) {
        float p[NEXP];
        float mx = -1e30f;
        #pragma unroll
        for (int e = 0; e < NEXP; e++) mx = fmaxf(mx, logits[e]);
        float sum = 0.f;
        #pragma unroll
        for (int e = 0; e < NEXP; e++) { p[e] = expf(logits[e] - mx); sum += p[e]; }
        float inv = 1.f / sum;
        #pragma unroll
        for (int e = 0; e < NEXP; e++) p[e] *= inv;

        float tv[TOPK]; int ti[TOPK];
        #pragma unroll
        for (int k = 0; k < TOPK; k++) {
            float best = -1.f; int bi = 0;
            #pragma unroll
            for (int e = 0; e < NEXP; e++)
                if (p[e] > best) { best = p[e]; bi = e; }
            tv[k] = best; ti[k] = bi; p[bi] = -1.f;
        }
        float s8 = 0.f;
        #pragma unroll
        for (int k = 0; k < TOPK; k++) s8 += tv[k];
        float invs8 = 1.f / fmaxf(s8, 1e-12f);
        float cum = 0.f; int cnt_lt = 0;
        #pragma unroll
        for (int k = 0; k < TOPK; k++) {
            cum += tv[k] * invs8;
            if (cum < THRESH) cnt_lt++;
        }
        int keep = min(cnt_lt + 1, TOPK);
        float ssel = 0.f;
        for (int k = 0; k < keep; k++) ssel += tv[k];
        float invsel = 1.f / fmaxf(ssel, 1e-12f);
        g_tok_nkeep[t] = keep;
        for (int k = 0; k < keep; k++) {
            int e = ti[k];
            int slot = atomicAdd(&g_count[e], 1);
            g_tokens[e][slot]   = t;
            g_tok_expert[t][k]  = e;
            g_tok_slot[t][k]    = slot;
            g_tok_w[t][k]       = tv[k] * invsel;
        }
    }
}

// ---------------- mma.sync tf32 grouped GEMM, 128thr x 4 CTAs/SM -------------
// R14 tiling (4 warps 2x2; warp 32x(32|64); BM=64; 2-deep rings) with an
// mbarrier full/empty protocol instead of cp.async groups + 2 syncthreads:
// full[b] armed by each thread's cp.async via cp.async.mbarrier.arrive.NOINC
// (consumes the 128-count), waited a full stage later (fast-path); empty[b]
// is the single real rendezvous before re-staging slot b. Parities from s.
// B operands RAW fp32 bits (tf32 truncation compensated by LAMBDA on A side).
template<bool FUSED>
__global__ __launch_bounds__(128, 4)
void moe_mma(const float* __restrict__ W) {
    constexpr int KDIM = FUSED ? HID : INTER_SZ;
    constexpr int NS   = KDIM / TK;              // 64 or 24
    constexpr int BNK  = FUSED ? 64 : 128;       // B0 rows per tile
    constexpr int NJ   = FUSED ? 4 : 8;          // 8-col mma tiles per warp
    constexpr int NJ1  = FUSED ? 4 : 1;
    constexpr int WN   = FUSED ? 32 : 64;        // warp N extent
    constexpr int NA   = 4;                      // A chunks/thread (64*8/128)
    constexpr int NB0  = BNK * 8 / 128;          // 4 or 8
    constexpr int BROWS = 128;                   // total B rows staged (B0[+B1])
    constexpr int BARS_F = 2 * (BM + BROWS) * ROWF;  // float offset of barriers

    const int e   = blockIdx.z;
    const int cnt = g_count[e];
    const int m0  = blockIdx.y * BM;
    if (m0 >= cnt) return;
    const int n0  = blockIdx.x * BNK;

    extern __shared__ float smf[];
    int*  toks = (int*)(smf + BARS_F + 8);       // after 4 mbarriers (32B)

    const int tid  = threadIdx.x;
    const int lane = tid & 31, wid = tid >> 5;
    const int warp_m = wid & 1, warp_n = wid >> 1;           // 2 x 2 warps

    const uint32_t sa   = smem_u32(smf);
    const uint32_t full0  = sa + BARS_F * 4;
    const uint32_t full1  = full0 + 8;
    const uint32_t empty0 = full0 + 16;
    const uint32_t empty1 = full0 + 24;

    if (tid == 0) {
        MBAR_INIT(full0, 128); MBAR_INIT(full1, 128);
        MBAR_INIT(empty0, 128); MBAR_INIT(empty1, 128);
    }
    if (FUSED && tid < BM) {
        int r = m0 + tid;
        toks[tid] = (r < cnt) ? g_tokens[e][r] : g_tokens[e][0];
    }
    __syncthreads();

    const uint32_t aAs = sa;                                 // A: [2][64][ROWF]
    const uint32_t aB0 = sa + 2 * BM * ROWF * 4;             // B0: [2][BNK][ROWF]
    const uint32_t aB1 = aB0 + 2 * BNK * ROWF * 4;           // B1 (FUSED): [2][64][ROWF]

    const float* Wb = W + (size_t)e * (FUSED ? (size_t)NGU * HID : (size_t)HID * INTER_SZ)
                        + (size_t)n0 * KDIM;
    const float* Wu = FUSED ? (W + (size_t)e * NGU * HID + (size_t)(INTER_SZ + n0) * HID)
                            : (const float*)nullptr;

    // per-thread ldsm base offsets (bytes within a buffer)
    const int grp = lane >> 3, rr = lane & 7;
    const uint32_t abase = (uint32_t)(((warp_m * 32 + (grp & 1) * 8 + rr) * ROWF
                                       + (grp >> 1) * 4) * 4);
    const uint32_t bbase = (uint32_t)(((warp_n * WN + (grp >> 1) * 8 + rr) * ROWF
                                       + (grp & 1) * 4) * 4);

    // ---- A + B staging via cp.async into ring slot s&1 ----
    auto stage = [&](int s) {
        const int buf = s & 1;
        const int k0  = s * TK;
        const uint32_t bufA = aAs + buf * BM * ROWF * 4;
        #pragma unroll
        for (int i = 0; i < NA; i++) {                       // A: 512 chunks / 128 thr
            int c = tid + i * 128; int row = c >> 3, q = c & 7;
            const float* src;
            if (FUSED) {
                src = &g_xcvt[toks[row]][k0 + q * 4];
            } else {
                int r = m0 + row; if (r >= cnt) r = m0;
                src = &g_h[e][r][k0 + q * 4];
            }
            cpasync16(bufA + (row * ROWF + q * 4) * 4, src);
        }
        const uint32_t bufB0 = aB0 + buf * BNK * ROWF * 4;
        #pragma unroll
        for (int i = 0; i < NB0; i++) {                      // B0: BNK*8 chunks
            int c = tid + i * 128; int row = c >> 3, q = c & 7;
            cpasync16(bufB0 + (row * ROWF + q * 4) * 4,
                      Wb + (size_t)row * KDIM + k0 + q * 4);
        }
        if (FUSED) {
            const uint32_t bufB1 = aB1 + buf * 64 * ROWF * 4;
            #pragma unroll
            for (int i = 0; i < 4; i++) {                    // B1: 512 chunks
                int c = tid + i * 128; int row = c >> 3, q = c & 7;
                cpasync16(bufB1 + (row * ROWF + q * 4) * 4,
                          Wu + (size_t)row * KDIM + k0 + q * 4);
            }
        }
    };

    float acc0[2][NJ][4] = {};
    float acc1[2][NJ1][4] = {};

    // ---- prologue: arm both ring slots ----
    stage(0); CPASYNC_MBAR_ARRIVE(full0);
    stage(1); CPASYNC_MBAR_ARRIVE(full1);

    for (int s = 0; s < NS; s++) {
        const int b = s & 1;
        const uint32_t ph = (uint32_t)((s >> 1) & 1);
        mbar_wait(b ? full1 : full0, ph);        // data ready (armed a stage ago)

        const uint32_t bufA  = aAs + b * BM * ROWF * 4;
        const uint32_t bufB0 = aB0 + b * BNK * ROWF * 4;
        const uint32_t bufB1 = aB1 + b * 64 * ROWF * 4;

        #pragma unroll
        for (int kk = 0; kk < 4; kk++) {
            uint32_t a[2][4];
            #pragma unroll
            for (int i = 0; i < 2; i++)
                ldsm4(a[i][0], a[i][1], a[i][2], a[i][3],
                      bufA + abase + i * 16 * ROWF * 4 + kk * 32);
            uint32_t b0[NJ][2];
            #pragma unroll
            for (int jp = 0; jp < NJ / 2; jp++)
                ldsm4(b0[2 * jp][0], b0[2 * jp][1], b0[2 * jp + 1][0], b0[2 * jp + 1][1],
                      bufB0 + bbase + jp * 16 * ROWF * 4 + kk * 32);
            uint32_t b1[NJ1][2];
            if (FUSED) {
                #pragma unroll
                for (int jp = 0; jp < NJ1 / 2; jp++)
                    ldsm4(b1[2 * jp][0], b1[2 * jp][1], b1[2 * jp + 1][0], b1[2 * jp + 1][1],
                          bufB1 + bbase + jp * 16 * ROWF * 4 + kk * 32);
            }
            #pragma unroll
            for (int i = 0; i < 2; i++)
                #pragma unroll
                for (int j = 0; j < NJ; j++) {
                    mma8(acc0[i][j], a[i], b0[j]);
                    if (FUSED) mma8(acc1[i][j % NJ1], a[i], b1[j % NJ1]);
                }
        }

        MBAR_ARRIVE(b ? empty1 : empty0);        // this thread done reading buf b
        if (s + 2 < NS) {
            mbar_wait(b ? empty1 : empty0, ph);  // ALL readers done with buf b
            stage(s + 2);                        // overwrite slot b
            CPASYNC_MBAR_ARRIVE(b ? full1 : full0);
        }
    }

    // ---- epilogue ----
    #pragma unroll
    for (int i = 0; i < 2; i++) {
        int r0 = m0 + warp_m * 32 + i * 16 + (lane >> 2);
        #pragma unroll
        for (int j = 0; j < NJ; j++) {
            int col = n0 + warp_n * WN + j * 8 + 2 * (lane & 3);
            if (FUSED) {
                if (r0 < cnt) {
                    float2 v;
                    v.x = __uint_as_float(cvt_tf32(LAMBDA * silu(acc0[i][j][0]) * acc1[i][j % NJ1][0]));
                    v.y = __uint_as_float(cvt_tf32(LAMBDA * silu(acc0[i][j][1]) * acc1[i][j % NJ1][1]));
                    *(float2*)&g_h[e][r0][col] = v;
                }
                if (r0 + 8 < cnt) {
                    float2 v;
                    v.x = __uint_as_float(cvt_tf32(LAMBDA * silu(acc0[i][j][2]) * acc1[i][j % NJ1][2]));
                    v.y = __uint_as_float(cvt_tf32(LAMBDA * silu(acc0[i][j][3]) * acc1[i][j % NJ1][3]));
                    *(float2*)&g_h[e][r0 + 8][col] = v;
                }
            } else {
                if (r0 < cnt) {
                    float2 v = make_float2(acc0[i][j][0], acc0[i][j][1]);
                    *(float2*)&g_downbuf[((size_t)e * T_TOKENS + r0) * HID + col] = v;
                }
                if (r0 + 8 < cnt) {
                    float2 v = make_float2(acc0[i][j][2], acc0[i][j][3]);
                    *(float2*)&g_downbuf[((size_t)e * T_TOKENS + r0 + 8) * HID + col] = v;
                }
            }
        }
    }
}

// ---------------- kernel 4: deterministic per-token combine -----------------
__global__ void combine_kernel(float* __restrict__ out) {
    int t = blockIdx.x;
    int nk = g_tok_nkeep[t];
    int   es[TOPK], ss[TOPK];
    float ws[TOPK];
    for (int k = 0; k < nk; k++) {
        es[k] = g_tok_expert[t][k];
        ss[k] = g_tok_slot[t][k];
        ws[k] = g_tok_w[t][k];
    }
    for (int h = threadIdx.x * 4; h < HID; h += blockDim.x * 4) {
        float4 acc = make_float4(0.f, 0.f, 0.f, 0.f);
        for (int k = 0; k < nk; k++) {
            const float4 v = *(const float4*)
                &g_downbuf[((size_t)es[k] * T_TOKENS + ss[k]) * HID + h];
            acc.x += ws[k] * v.x; acc.y += ws[k] * v.y;
            acc.z += ws[k] * v.z; acc.w += ws[k] * v.w;
        }
        *(float4*)&out[(size_t)t * HID + h] = acc;
    }
}

// ---------------- launch ----------------------------------------------------
// rings 2 x (A 64 + B 128 rows) x ROWF floats = 13824 floats (55296B)
// + 32B mbarriers + 256B toks = 55584B; 4 CTAs/SM (222.3KB < 228KB)
#define SMEM_BYTES (2 * (64 + 128) * ROWF * 4 + 32 + 64 * 4)

extern "C" void kernel_launch(void* const* d_in, const int* in_sizes, int n_in,
                              void* d_out, int out_size) {
    const float* hidden  = (const float*)d_in[0];   // [2,1024,2048]
    const float* gate_w  = (const float*)d_in[1];   // [32,2048]
    const float* gate_up = (const float*)d_in[2];   // [32,1536,2048]
    const float* down_w  = (const float*)d_in[3];   // [32,2048,768]
    float* out = (float*)d_out;

    cudaFuncSetAttribute(moe_mma<true>,  cudaFuncAttributeMaxDynamicSharedMemorySize, SMEM_BYTES);
    cudaFuncSetAttribute(moe_mma<false>, cudaFuncAttributeMaxDynamicSharedMemorySize, SMEM_BYTES);

    zero_counts_kernel<<<1, 32>>>();
    router_kernel<<<T_TOKENS, 256>>>(hidden, gate_w);
    {
        dim3 grid(INTER_SZ / 64, T_TOKENS / BM, NEXP);    // (12, 32, 32)
        moe_mma<true><<<grid, 128, SMEM_BYTES>>>(gate_up);
    }
    {
        dim3 grid(HID / 128, T_TOKENS / BM, NEXP);        // (16, 32, 32)
        moe_mma<false><<<grid, 128, SMEM_BYTES>>>(down_w);
    }
    combine_kernel<<<T_TOKENS, 256>>>(out);
}